// round 15
// baseline (speedup 1.0000x reference)
#include <cuda_runtime.h>
#include <math.h>
#include <mma.h>

using namespace nvcuda;

#define BB 16
#define NNODE 512
#define EE 8192
#define CC 128
#define OHH 512
#define ROWS (BB*NNODE)   // 8192
#define HCM_LD 520        // channel-major conv1 out: 8 x 520 (514 used); 520%32=8 -> conflict-free

// GEMM tiling
#define GK_CK 32
#define AS_LD 40
#define BS_LD 72
#define G_SMEM_FLOATS (2*64*AS_LD + 2*GK_CK*BS_LD)

// ---------------- device scratch ----------------
__device__ int   g_cnt[ROWS];
__device__ int   g_off[ROWS];
__device__ int   g_elist[BB*EE];
__device__ float g_xcat[(size_t)ROWS*136];
__device__ float g_h1[(size_t)ROWS*128];
__device__ float g_sum[128];
__device__ float g_sq[128];

// ---------------- no-op kernel (profiler steering: k_fused = launch #4) ----------------
__global__ void k_nop() {}

// ---------------- CSR build: 1024 threads, one block per batch ----------------
__global__ void __launch_bounds__(1024) k_csr(const int* __restrict__ adjs)
{
    int b = blockIdx.x, t = threadIdx.x;
    __shared__ int cnt[NNODE];
    __shared__ int sc[NNODE];
    if (t < NNODE) cnt[t] = 0;
    if (b == 0 && t < 128) { g_sum[t] = 0.f; g_sq[t] = 0.f; }
    __syncthreads();

    const int* send = adjs + b * 2 * EE;
    const int* recv = send + EE;
    #pragma unroll 4
    for (int e = t; e < EE; e += 1024) atomicAdd(&cnt[recv[e]], 1);
    __syncthreads();

    int v0 = (t < NNODE) ? cnt[t] : 0;
    if (t < NNODE) sc[t] = v0;
    __syncthreads();
    for (int d = 1; d < NNODE; d <<= 1) {
        int add = (t < NNODE && t >= d) ? sc[t - d] : 0;
        __syncthreads();
        if (t < NNODE) sc[t] += add;
        __syncthreads();
    }
    if (t < NNODE) {
        int excl = sc[t] - v0;
        g_off[b * NNODE + t] = excl;
        g_cnt[b * NNODE + t] = v0;
        cnt[t] = excl;
    }
    __syncthreads();

    #pragma unroll 4
    for (int e = t; e < EE; e += 1024) {
        int r = recv[e];
        int pos = atomicAdd(&cnt[r], 1);
        g_elist[b * EE + pos] = send[e];
    }
}

__device__ __forceinline__ void ce(float& a, float& b, bool up) {
    float mn = fminf(a, b), mx = fmaxf(a, b);
    a = up ? mn : mx;
    b = up ? mx : mn;
}

__device__ __forceinline__ void mma_tf32(float c[4], const unsigned a[4], const unsigned b[2]) {
    asm volatile(
        "mma.sync.aligned.m16n8k8.row.col.f32.tf32.tf32.f32 "
        "{%0,%1,%2,%3}, {%4,%5,%6,%7}, {%8,%9}, {%0,%1,%2,%3};\n"
        : "+f"(c[0]), "+f"(c[1]), "+f"(c[2]), "+f"(c[3])
        : "r"(a[0]), "r"(a[1]), "r"(a[2]), "r"(a[3]), "r"(b[0]), "r"(b[1]));
}

// ---------------- fused per-node kernel: 1 node / 128 threads ----------------
__global__ void __launch_bounds__(128) k_fused(
    const float* __restrict__ xs, const float* __restrict__ oh,
    const float* __restrict__ c1w_g, const float* __restrict__ c1b_g,
    const float* __restrict__ c2w_g, const float* __restrict__ c2b_g,
    const float* __restrict__ lw_g,  const float* __restrict__ lb_g,
    float* __restrict__ newoh)
{
    extern __shared__ float dsm[];
    float* hcm = dsm;                  // [8][HCM_LD] channel-major, tf32-rounded conv1 out

    __shared__ float soh[512];
    __shared__ float wc1s[24], bc1s[8], bc2s[16];
    __shared__ float meansh[16];

    int t = threadIdx.x;
    int node = blockIdx.x;
    int b = node >> 9, n = node & 511;

    if (t < 24) wc1s[t] = c1w_g[t];
    if (t < 8)  bc1s[t] = c1b_g[t];
    if (t < 16) { bc2s[t] = c2b_g[t]; meansh[t] = 0.f; }

    // ---- gather ----
    const float4* ohb4 = reinterpret_cast<const float4*>(oh + (size_t)b * NNODE * OHH);
    const float*  xb   = xs + (size_t)b * NNODE * CC;
    int off = g_off[node];
    int m   = g_cnt[node];
    const int* el = &g_elist[b * EE + off];

    float4 a = ohb4[(size_t)n * 128 + t];
    float  ax = xb[n * CC + t];
    int i = 0;
    for (; i + 4 <= m; i += 4) {
        int s0 = el[i], s1 = el[i+1], s2 = el[i+2], s3 = el[i+3];
        float4 r0 = ohb4[(size_t)s0 * 128 + t];
        float4 r1 = ohb4[(size_t)s1 * 128 + t];
        float4 r2 = ohb4[(size_t)s2 * 128 + t];
        float4 r3 = ohb4[(size_t)s3 * 128 + t];
        a.x += r0.x + r1.x + r2.x + r3.x;
        a.y += r0.y + r1.y + r2.y + r3.y;
        a.z += r0.z + r1.z + r2.z + r3.z;
        a.w += r0.w + r1.w + r2.w + r3.w;
        ax  += xb[s0 * CC + t] + xb[s1 * CC + t] + xb[s2 * CC + t] + xb[s3 * CC + t];
    }
    for (; i < m; i++) {
        int s = el[i];
        float4 r0 = ohb4[(size_t)s * 128 + t];
        a.x += r0.x; a.y += r0.y; a.z += r0.z; a.w += r0.w;
        ax  += xb[s * CC + t];
    }
    reinterpret_cast<float4*>(newoh + (size_t)node * OHH)[t] = a;
    g_xcat[(size_t)node * 136 + t] = ax;

    // ---- bitonic sort: 512 elems, 4/thread ----
    float v0 = a.x, v1 = a.y, v2 = a.z, v3 = a.w;

    ce(v0, v1, true);
    ce(v2, v3, false);

    #pragma unroll
    for (int k = 4; k <= 512; k <<= 1) {
        bool up = (((4 * t) & k) == 0);

        for (int j = k >> 1; j >= 128; j >>= 1) {
            soh[4*t]   = v0; soh[4*t+1] = v1;
            soh[4*t+2] = v2; soh[4*t+3] = v3;
            __syncthreads();
            #pragma unroll
            for (int r = 0; r < 4; r++) {
                int idx = 4 * t + r;
                float p = soh[idx ^ j];
                bool lower = ((idx & j) == 0);
                float cur = (r == 0) ? v0 : (r == 1) ? v1 : (r == 2) ? v2 : v3;
                float nv = (lower == up) ? fminf(cur, p) : fmaxf(cur, p);
                if (r == 0) v0 = nv; else if (r == 1) v1 = nv; else if (r == 2) v2 = nv; else v3 = nv;
            }
            __syncthreads();
        }

        int jstart = (k >> 1) > 64 ? 64 : (k >> 1);
        for (int j = jstart; j >= 4; j >>= 1) {
            int lx = j >> 2;
            bool lower = ((t & lx) == 0);
            bool keepmin = (lower == up);
            float p0 = __shfl_xor_sync(0xffffffffu, v0, lx);
            float p1 = __shfl_xor_sync(0xffffffffu, v1, lx);
            float p2 = __shfl_xor_sync(0xffffffffu, v2, lx);
            float p3 = __shfl_xor_sync(0xffffffffu, v3, lx);
            v0 = keepmin ? fminf(v0, p0) : fmaxf(v0, p0);
            v1 = keepmin ? fminf(v1, p1) : fmaxf(v1, p1);
            v2 = keepmin ? fminf(v2, p2) : fmaxf(v2, p2);
            v3 = keepmin ? fminf(v3, p3) : fmaxf(v3, p3);
        }

        ce(v0, v2, up); ce(v1, v3, up);
        ce(v0, v1, up); ce(v2, v3, up);
    }

    // ---- symlog + publish sorted row ----
    v0 = copysignf(log1pf(fabsf(v0)), v0);
    v1 = copysignf(log1pf(fabsf(v1)), v1);
    v2 = copysignf(log1pf(fabsf(v2)), v2);
    v3 = copysignf(log1pf(fabsf(v3)), v3);
    soh[4*t] = v0; soh[4*t+1] = v1; soh[4*t+2] = v2; soh[4*t+3] = v3;
    __syncthreads();

    // ---- conv1 ----
    #pragma unroll
    for (int r = 0; r < 4; r++) {
        int p = t + 128 * r;
        float pm = (p > 0)   ? soh[p - 1] : 0.f;
        float pc = soh[p];
        float pp = (p < 511) ? soh[p + 1] : 0.f;
        #pragma unroll
        for (int c = 0; c < 8; c++) {
            float h = fmaxf(fmaf(wc1s[c*3], pm, fmaf(wc1s[c*3+1], pc, fmaf(wc1s[c*3+2], pp, bc1s[c]))), 0.f);
            hcm[c * HCM_LD + p + 1] = wmma::__float_to_tf32(h);
        }
    }
    if (t < 16) {
        if (t < 8) hcm[t * HCM_LD] = 0.f;
        else       hcm[(t - 8) * HCM_LD + 513] = 0.f;
    }
    __syncthreads();

    // ---- conv2 via mma.sync; B-fragments loaded per-lane directly from global ----
    int lane = t & 31;
    int ww = t >> 5;
    int gid = lane >> 2, tg = lane & 3;

    // bfr[tau][h][kk]: B element (k = tg + 4*kk, col = 8h + gid), tf32-rounded
    unsigned bfr[3][2][2];
    #pragma unroll
    for (int tau = 0; tau < 3; tau++)
        #pragma unroll
        for (int h = 0; h < 2; h++) {
            int oc = 8 * h + gid;
            bfr[tau][h][0] = __float_as_uint(wmma::__float_to_tf32(c2w_g[oc * 24 + tg * 3 + tau]));
            bfr[tau][h][1] = __float_as_uint(wmma::__float_to_tf32(c2w_g[oc * 24 + (tg + 4) * 3 + tau]));
        }
    float bias[2][2];
    #pragma unroll
    for (int h = 0; h < 2; h++) {
        bias[h][0] = bc2s[8*h + 2*tg];
        bias[h][1] = bc2s[8*h + 2*tg + 1];
    }

    float s[2][2] = {{0.f, 0.f}, {0.f, 0.f}};

    #pragma unroll
    for (int tile = 0; tile < 8; tile++) {
        int p0 = (ww * 8 + tile) * 16;
        float c0[4] = {0.f, 0.f, 0.f, 0.f};
        float c1[4] = {0.f, 0.f, 0.f, 0.f};
        #pragma unroll
        for (int tau = 0; tau < 3; tau++) {
            int p = p0 + tau;
            unsigned afr[4];
            afr[0] = __float_as_uint(hcm[tg * HCM_LD + p + gid]);
            afr[1] = __float_as_uint(hcm[tg * HCM_LD + p + gid + 8]);
            afr[2] = __float_as_uint(hcm[(tg + 4) * HCM_LD + p + gid]);
            afr[3] = __float_as_uint(hcm[(tg + 4) * HCM_LD + p + gid + 8]);
            mma_tf32(c0, afr, bfr[tau][0]);
            mma_tf32(c1, afr, bfr[tau][1]);
        }
        s[0][0] += fmaxf(c0[0] + bias[0][0], 0.f) + fmaxf(c0[2] + bias[0][0], 0.f);
        s[0][1] += fmaxf(c0[1] + bias[0][1], 0.f) + fmaxf(c0[3] + bias[0][1], 0.f);
        s[1][0] += fmaxf(c1[0] + bias[1][0], 0.f) + fmaxf(c1[2] + bias[1][0], 0.f);
        s[1][1] += fmaxf(c1[1] + bias[1][1], 0.f) + fmaxf(c1[3] + bias[1][1], 0.f);
    }
    #pragma unroll
    for (int d = 4; d <= 16; d <<= 1) {
        s[0][0] += __shfl_xor_sync(0xffffffffu, s[0][0], d);
        s[0][1] += __shfl_xor_sync(0xffffffffu, s[0][1], d);
        s[1][0] += __shfl_xor_sync(0xffffffffu, s[1][0], d);
        s[1][1] += __shfl_xor_sync(0xffffffffu, s[1][1], d);
    }
    if (gid == 0) {
        atomicAdd(&meansh[2*tg],     s[0][0]);
        atomicAdd(&meansh[2*tg + 1], s[0][1]);
        atomicAdd(&meansh[8 + 2*tg],     s[1][0]);
        atomicAdd(&meansh[8 + 2*tg + 1], s[1][1]);
    }
    __syncthreads();

    if (t < 8) {
        float acc = lb_g[t];
        #pragma unroll
        for (int oc = 0; oc < 16; oc++) acc = fmaf(meansh[oc] * (1.f / 512.f), lw_g[oc * 8 + t], acc);
        g_xcat[(size_t)node * 136 + 128 + t] = acc;
    }
}

// ---------------- GEMM1: 3xTF32 mma, 64x64 tiles, 256 blocks ----------------
__global__ void __launch_bounds__(256) k_gemm1(
    const float* __restrict__ w1, const float* __restrict__ b1)
{
    extern __shared__ float sm[];
    float* as_hi = sm;
    float* as_lo = as_hi + 64 * AS_LD;
    float* bs_hi = as_lo + 64 * AS_LD;
    float* bs_lo = bs_hi + GK_CK * BS_LD;
    __shared__ float sb[64];

    int tid = threadIdx.x;
    int col0 = (blockIdx.x & 1) * 64;
    int row0 = (blockIdx.x >> 1) * 64;
    if (tid < 64) sb[tid] = b1[col0 + tid];

    int w = tid >> 5, lane = tid & 31, gid = lane >> 2, tg = lane & 3;
    int m0w = (w & 3) * 16, n0w = (w >> 2) * 32;

    float c[4][4];
    #pragma unroll
    for (int f = 0; f < 4; f++)
        #pragma unroll
        for (int q = 0; q < 4; q++) c[f][q] = 0.f;

    for (int k0 = 0; k0 < 136; k0 += GK_CK) {
        __syncthreads();
        #pragma unroll
        for (int idx = tid; idx < 64 * GK_CK; idx += 256) {
            int r = idx >> 5, kk = idx & 31, k = k0 + kk;
            float v = (k < 136) ? g_xcat[(size_t)(row0 + r) * 136 + k] : 0.f;
            float hi = wmma::__float_to_tf32(v);
            as_hi[r * AS_LD + kk] = hi;
            as_lo[r * AS_LD + kk] = wmma::__float_to_tf32(v - hi);
        }
        #pragma unroll
        for (int idx = tid; idx < GK_CK * 64; idx += 256) {
            int kk = idx >> 6, nn2 = idx & 63, k = k0 + kk;
            float v = (k < 136) ? w1[(size_t)k * 128 + col0 + nn2] : 0.f;
            float hi = wmma::__float_to_tf32(v);
            bs_hi[kk * BS_LD + nn2] = hi;
            bs_lo[kk * BS_LD + nn2] = wmma::__float_to_tf32(v - hi);
        }
        __syncthreads();
        int kmax = (136 - k0 < GK_CK) ? (136 - k0) : GK_CK;
        for (int kb = 0; kb < kmax; kb += 8) {
            unsigned ah[4], al[4];
            int ab = (m0w + gid) * AS_LD + kb;
            ah[0] = __float_as_uint(as_hi[ab + tg]);
            ah[1] = __float_as_uint(as_hi[ab + 8 * AS_LD + tg]);
            ah[2] = __float_as_uint(as_hi[ab + tg + 4]);
            ah[3] = __float_as_uint(as_hi[ab + 8 * AS_LD + tg + 4]);
            al[0] = __float_as_uint(as_lo[ab + tg]);
            al[1] = __float_as_uint(as_lo[ab + 8 * AS_LD + tg]);
            al[2] = __float_as_uint(as_lo[ab + tg + 4]);
            al[3] = __float_as_uint(as_lo[ab + 8 * AS_LD + tg + 4]);
            #pragma unroll
            for (int f = 0; f < 4; f++) {
                int bb = (kb + tg) * BS_LD + n0w + f * 8 + gid;
                unsigned bh[2], blo[2];
                bh[0]  = __float_as_uint(bs_hi[bb]);
                bh[1]  = __float_as_uint(bs_hi[bb + 4 * BS_LD]);
                blo[0] = __float_as_uint(bs_lo[bb]);
                blo[1] = __float_as_uint(bs_lo[bb + 4 * BS_LD]);
                mma_tf32(c[f], ah, bh);
                mma_tf32(c[f], al, bh);
                mma_tf32(c[f], ah, blo);
            }
        }
    }
    #pragma unroll
    for (int f = 0; f < 4; f++) {
        int nloc = n0w + f * 8 + 2 * tg;
        int gcol = col0 + nloc;
        int r0 = row0 + m0w + gid;
        float2 v01 = make_float2(c[f][0] + sb[nloc], c[f][1] + sb[nloc + 1]);
        float2 v23 = make_float2(c[f][2] + sb[nloc], c[f][3] + sb[nloc + 1]);
        *reinterpret_cast<float2*>(&g_h1[(size_t)r0 * 128 + gcol]) = v01;
        *reinterpret_cast<float2*>(&g_h1[(size_t)(r0 + 8) * 128 + gcol]) = v23;
    }
}

// ---------------- masked BN stats over h1 ----------------
__global__ void __launch_bounds__(256) k_bnstats(const int* __restrict__ n_nodes)
{
    __shared__ int nn[16];
    __shared__ float rs[256], rq[256];
    int tid = threadIdx.x;
    if (tid < 16) nn[tid] = n_nodes[tid];
    __syncthreads();
    int c = tid & 127, h = tid >> 7;
    int row0 = blockIdx.x * 128 + h * 64;
    float s = 0.f, q = 0.f;
    for (int r = 0; r < 64; r++) {
        int row = row0 + r;
        float v = g_h1[(size_t)row * 128 + c];
        if ((row & 511) < nn[row >> 9]) { s += v; q += v * v; }
    }
    rs[tid] = s; rq[tid] = q;
    __syncthreads();
    if (tid < 128) {
        atomicAdd(&g_sum[c], rs[tid] + rs[tid + 128]);
        atomicAdd(&g_sq[c],  rq[tid] + rq[tid + 128]);
    }
}

// ---------------- GEMM2: 3xTF32 mma, BN finalize+affine+relu fused, mask on store ----------------
__global__ void __launch_bounds__(256) k_gemm2(
    const float* __restrict__ w2, const float* __restrict__ b2,
    const int* __restrict__ n_nodes,
    const float* __restrict__ bng, const float* __restrict__ bnb,
    float* __restrict__ outp)
{
    extern __shared__ float sm[];
    float* as_hi = sm;
    float* as_lo = as_hi + 64 * AS_LD;
    float* bs_hi = as_lo + 64 * AS_LD;
    float* bs_lo = bs_hi + GK_CK * BS_LD;
    __shared__ float sb[64], sa[128], sc2[128];
    __shared__ int nn[16];

    int tid = threadIdx.x;
    int col0 = (blockIdx.x & 1) * 64;
    int row0 = (blockIdx.x >> 1) * 64;
    if (tid < 16) nn[tid] = n_nodes[tid];
    if (tid < 64) sb[tid] = b2[col0 + tid];
    __syncthreads();
    if (tid < 128) {
        int s = 0;
        #pragma unroll
        for (int bb2 = 0; bb2 < 16; bb2++) s += nn[bb2];
        float cntf = fmaxf((float)s, 1.f);
        float mean = g_sum[tid] / cntf;
        float var  = g_sq[tid] / cntf - mean * mean;
        float aa = rsqrtf(var + 1e-5f) * bng[tid];
        sa[tid] = aa;
        sc2[tid] = bnb[tid] - mean * aa;
    }
    __syncthreads();

    int w = tid >> 5, lane = tid & 31, gid = lane >> 2, tg = lane & 3;
    int m0w = (w & 3) * 16, n0w = (w >> 2) * 32;

    float c[4][4];
    #pragma unroll
    for (int f = 0; f < 4; f++)
        #pragma unroll
        for (int q = 0; q < 4; q++) c[f][q] = 0.f;

    for (int k0 = 0; k0 < 128; k0 += GK_CK) {
        __syncthreads();
        #pragma unroll
        for (int idx = tid; idx < 64 * GK_CK; idx += 256) {
            int r = idx >> 5, kk = idx & 31, k = k0 + kk;
            float hv = g_h1[(size_t)(row0 + r) * 128 + k];
            float v = fmaxf(fmaf(hv, sa[k], sc2[k]), 0.f);
            float hi = wmma::__float_to_tf32(v);
            as_hi[r * AS_LD + kk] = hi;
            as_lo[r * AS_LD + kk] = wmma::__float_to_tf32(v - hi);
        }
        #pragma unroll
        for (int idx = tid; idx < GK_CK * 64; idx += 256) {
            int kk = idx >> 6, nn2 = idx & 63, k = k0 + kk;
            float v = w2[(size_t)k * 128 + col0 + nn2];
            float hi = wmma::__float_to_tf32(v);
            bs_hi[kk * BS_LD + nn2] = hi;
            bs_lo[kk * BS_LD + nn2] = wmma::__float_to_tf32(v - hi);
        }
        __syncthreads();
        for (int kb = 0; kb < GK_CK; kb += 8) {
            unsigned ah[4], al[4];
            int ab = (m0w + gid) * AS_LD + kb;
            ah[0] = __float_as_uint(as_hi[ab + tg]);
            ah[1] = __float_as_uint(as_hi[ab + 8 * AS_LD + tg]);
            ah[2] = __float_as_uint(as_hi[ab + tg + 4]);
            ah[3] = __float_as_uint(as_hi[ab + 8 * AS_LD + tg + 4]);
            al[0] = __float_as_uint(as_lo[ab + tg]);
            al[1] = __float_as_uint(as_lo[ab + 8 * AS_LD + tg]);
            al[2] = __float_as_uint(as_lo[ab + tg + 4]);
            al[3] = __float_as_uint(as_lo[ab + 8 * AS_LD + tg + 4]);
            #pragma unroll
            for (int f = 0; f < 4; f++) {
                int bb = (kb + tg) * BS_LD + n0w + f * 8 + gid;
                unsigned bh[2], blo[2];
                bh[0]  = __float_as_uint(bs_hi[bb]);
                bh[1]  = __float_as_uint(bs_hi[bb + 4 * BS_LD]);
                blo[0] = __float_as_uint(bs_lo[bb]);
                blo[1] = __float_as_uint(bs_lo[bb + 4 * BS_LD]);
                mma_tf32(c[f], ah, bh);
                mma_tf32(c[f], al, bh);
                mma_tf32(c[f], ah, blo);
            }
        }
    }
    #pragma unroll
    for (int f = 0; f < 4; f++) {
        int nloc = n0w + f * 8 + 2 * tg;
        int gcol = col0 + nloc;
        int r0 = row0 + m0w + gid;
        bool mk0 = (r0 & 511) < nn[r0 >> 9];
        bool mk1 = ((r0 + 8) & 511) < nn[(r0 + 8) >> 9];
        float2 v01 = mk0 ? make_float2(c[f][0] + sb[nloc], c[f][1] + sb[nloc + 1])
                         : make_float2(0.f, 0.f);
        float2 v23 = mk1 ? make_float2(c[f][2] + sb[nloc], c[f][3] + sb[nloc + 1])
                         : make_float2(0.f, 0.f);
        *reinterpret_cast<float2*>(&outp[(size_t)r0 * 128 + gcol]) = v01;
        *reinterpret_cast<float2*>(&outp[(size_t)(r0 + 8) * 128 + gcol]) = v23;
    }
}

// ---------------- launcher ----------------
extern "C" void kernel_launch(void* const* d_in, const int* in_sizes, int n_in,
                              void* d_out, int out_size)
{
    const float* xs      = (const float*)d_in[0];
    const float* oh      = (const float*)d_in[1];
    const int*   adjs    = (const int*)d_in[2];
    const int*   n_nodes = (const int*)d_in[3];
    int w = (n_in >= 17) ? 5 : 4;   // skip dim_size scalar if present
    const float* c1w = (const float*)d_in[w + 0];
    const float* c1b = (const float*)d_in[w + 1];
    const float* c2w = (const float*)d_in[w + 2];
    const float* c2b = (const float*)d_in[w + 3];
    const float* lw  = (const float*)d_in[w + 4];
    const float* lb  = (const float*)d_in[w + 5];
    const float* w1  = (const float*)d_in[w + 6];
    const float* b1  = (const float*)d_in[w + 7];
    const float* bng = (const float*)d_in[w + 8];
    const float* bnb = (const float*)d_in[w + 9];
    const float* w2  = (const float*)d_in[w + 10];
    const float* b2  = (const float*)d_in[w + 11];

    float* outp  = (float*)d_out;
    float* newoh = outp + (size_t)ROWS * 128;

    const int FUSED_SMEM = (8 * HCM_LD) * 4;
    const int GEMM_SMEM  = G_SMEM_FLOATS * 4;
    cudaFuncSetAttribute(k_fused, cudaFuncAttributeMaxDynamicSharedMemorySize, FUSED_SMEM);
    cudaFuncSetAttribute(k_gemm1, cudaFuncAttributeMaxDynamicSharedMemorySize, GEMM_SMEM);
    cudaFuncSetAttribute(k_gemm2, cudaFuncAttributeMaxDynamicSharedMemorySize, GEMM_SMEM);

    k_csr  <<<16, 1024>>>(adjs);
    k_nop  <<<1, 32>>>();
    k_nop  <<<1, 32>>>();
    k_fused<<<ROWS, 128, FUSED_SMEM>>>(xs, oh, c1w, c1b, c2w, c2b, lw, lb, newoh);
    k_gemm1<<<256, 256, GEMM_SMEM>>>(w1, b1);
    k_bnstats<<<64, 256>>>(n_nodes);
    k_gemm2<<<256, 256, GEMM_SMEM>>>(w2, b2, n_nodes, bng, bnb, outp);
}